// round 14
// baseline (speedup 1.0000x reference)
#include <cuda_runtime.h>

// Problem constants (match reference)
#define MASK_P   0.15f
#define MASK_LEN 8
#define B_DIM    64
#define H_DIM    512
#define W_DIM    256
#define HW       (H_DIM * W_DIM)       // 131072 pixels (each = one float4)

#define TPB      256
#define BSPLIT   2                     // batch chunks (grid.y)
#define B_PER_T  (B_DIM / BSPLIT)      // 32 batches streamed per thread

// ---------------------------------------------------------------------------
// Fused kernel, BARRIER-FREE prologue: no shared memory, no __syncthreads.
// Each warp independently builds the mask for its 32 columns:
//   - starts loaded once per lane, broadcast via shfl (no reload, no smem)
//   - time-active batches via 2 ballots (h warp-uniform), expected ~1 active
//   - freq-candidate batches via 2 ballots (~10 of 64), predicated loads
// Warps never resynchronize -> no per-block pipe-drain bubbles.
// Stream: 32 batches, cs/cs (replicated win: 47.6/47.9 vs 51 for all else).
// launch_bounds(256,7): 7*148=1036 >= 1024 blocks (single wave), 36-reg cap.
// ---------------------------------------------------------------------------
__global__ __launch_bounds__(TPB, 7)
void fused_kernel(const float4* __restrict__ x,
                  const float4* __restrict__ time_rand,   // [B,8,W] of float4
                  const float4* __restrict__ freq_rand,   // [B,H,8] of float4
                  const int*    __restrict__ time_starts,
                  const int*    __restrict__ freq_starts,
                  float4*       __restrict__ out)
{
    const int tid  = threadIdx.x;
    const int pix  = blockIdx.x * TPB + tid;
    const int w    = pix & (W_DIM - 1);
    const int h    = pix >> 8;                 // uniform within block/warp
    const int lane = tid & 31;
    const int w0   = w & ~31;                  // warp's base column

    // Per-lane start values for batches lane and lane+32 (broadcast later).
    const int ts0 = __ldg(&time_starts[lane]);
    const int ts1 = __ldg(&time_starts[lane + 32]);
    const int fs0 = __ldg(&freq_starts[lane]);
    const int fs1 = __ldg(&freq_starts[lane + 32]);

    // Time-active ballots (h uniform -> flags uniform per lane's batch).
    unsigned act0 = __ballot_sync(0xFFFFFFFFu,
                        (unsigned)(h - ts0) < (unsigned)MASK_LEN ? 1u : 0u);
    unsigned act1 = __ballot_sync(0xFFFFFFFFu,
                        (unsigned)(h - ts1) < (unsigned)MASK_LEN ? 1u : 0u);

    // Freq-candidate ballots: batch b touches this warp iff
    // fs[b] in [w0-7, w0+31]  <=>  (fs - w0 + 7) in [0, 39).
    unsigned c0 = __ballot_sync(0xFFFFFFFFu,
                        (unsigned)(fs0 - w0 + (MASK_LEN - 1)) < (unsigned)(32 + MASK_LEN - 1) ? 1u : 0u);
    unsigned c1 = __ballot_sync(0xFFFFFFFFu,
                        (unsigned)(fs1 - w0 + (MASK_LEN - 1)) < (unsigned)(32 + MASK_LEN - 1) ? 1u : 0u);

    float4 m = make_float4(1.f, 1.f, 1.f, 1.f);

    // ---- time contributions (expected ~1 batch; coalesced row loads) ----
    while (act0) {
        int b = __ffs(act0) - 1;  act0 &= act0 - 1;
        int lt = h - __shfl_sync(0xFFFFFFFFu, ts0, b);      // in [0,8)
        float4 tr = __ldg(&time_rand[(b * MASK_LEN + lt) * W_DIM + w]);
        if (tr.x < MASK_P) m.x = 0.f;
        if (tr.y < MASK_P) m.y = 0.f;
        if (tr.z < MASK_P) m.z = 0.f;
        if (tr.w < MASK_P) m.w = 0.f;
    }
    while (act1) {
        int b = __ffs(act1) - 1;  act1 &= act1 - 1;
        int lt = h - __shfl_sync(0xFFFFFFFFu, ts1, b);
        float4 tr = __ldg(&time_rand[((b + 32) * MASK_LEN + lt) * W_DIM + w]);
        if (tr.x < MASK_P) m.x = 0.f;
        if (tr.y < MASK_P) m.y = 0.f;
        if (tr.z < MASK_P) m.z = 0.f;
        if (tr.w < MASK_P) m.w = 0.f;
    }

    // ---- freq contributions (~10 candidate batches; predicated loads) ----
    while (c0) {
        int b = __ffs(c0) - 1;  c0 &= c0 - 1;
        int lf = w - __shfl_sync(0xFFFFFFFFu, fs0, b);
        if ((unsigned)lf < (unsigned)MASK_LEN) {            // short arm
            float4 fr = __ldg(&freq_rand[((size_t)b * H_DIM + h) * MASK_LEN + lf]);
            if (fr.x < MASK_P) m.x = 0.f;
            if (fr.y < MASK_P) m.y = 0.f;
            if (fr.z < MASK_P) m.z = 0.f;
            if (fr.w < MASK_P) m.w = 0.f;
        }
    }
    while (c1) {
        int b = __ffs(c1) - 1;  c1 &= c1 - 1;
        int lf = w - __shfl_sync(0xFFFFFFFFu, fs1, b);
        if ((unsigned)lf < (unsigned)MASK_LEN) {
            float4 fr = __ldg(&freq_rand[((size_t)(b + 32) * H_DIM + h) * MASK_LEN + lf]);
            if (fr.x < MASK_P) m.x = 0.f;
            if (fr.y < MASK_P) m.y = 0.f;
            if (fr.z < MASK_P) m.z = 0.f;
            if (fr.w < MASK_P) m.w = 0.f;
        }
    }

    // ---- stream this chunk's 32 batches (cs/cs, replicated config) ----
    const int b0 = blockIdx.y * B_PER_T;
    const float4* __restrict__ xp = x   + (size_t)b0 * HW + pix;
    float4*       __restrict__ op = out + (size_t)b0 * HW + pix;

    #pragma unroll 16
    for (int b = 0; b < B_PER_T; ++b) {
        float4 v = __ldcs(&xp[b * HW]);
        v.x *= m.x; v.y *= m.y; v.z *= m.z; v.w *= m.w;
        __stcs(&op[b * HW], v);
    }
}

extern "C" void kernel_launch(void* const* d_in, const int* in_sizes, int n_in,
                              void* d_out, int out_size)
{
    const float4* x    = (const float4*)d_in[0];
    const float4* tr   = (const float4*)d_in[1];
    const float4* fr   = (const float4*)d_in[2];
    const int*    ts   = (const int*)d_in[3];
    const int*    fs   = (const int*)d_in[4];
    float4*       out  = (float4*)d_out;

    dim3 grid(HW / TPB, BSPLIT);              // 512 x 2 = 1024 blocks
    fused_kernel<<<grid, TPB>>>(x, tr, fr, ts, fs, out);
}

// round 15
// speedup vs baseline: 1.0477x; 1.0477x over previous
#include <cuda_runtime.h>

// Problem constants (match reference)
#define MASK_P   0.15f
#define MASK_LEN 8
#define B_DIM    64
#define H_DIM    512
#define W_DIM    256
#define HW       (H_DIM * W_DIM)       // 131072 pixels (each = one float4)

#define TPB      256
#define BSPLIT   4                     // batch chunks (grid.y) — A/B vs R13's 2
#define B_PER_T  (B_DIM / BSPLIT)      // 16 batches streamed per thread

// ---------------------------------------------------------------------------
// R13 structure with BSPLIT=4: finer block granularity (2048 blocks) gave the
// best measured stream DRAM% in R3 (72.5%); prologue is the distributed form
// measured ~free in R9; stream uses cs/cs (replicated 47.6/47.9 win).
// ---------------------------------------------------------------------------
__global__ __launch_bounds__(TPB, 8)
void fused_kernel(const float4* __restrict__ x,
                  const float4* __restrict__ time_rand,   // [B,8,W] of float4
                  const float4* __restrict__ freq_rand,   // [B,H,8] of float4
                  const int*    __restrict__ time_starts,
                  const int*    __restrict__ freq_starts,
                  float4*       __restrict__ out)
{
    const int tid = threadIdx.x;
    const int pix = blockIdx.x * TPB + tid;
    const int w   = pix & (W_DIM - 1);
    const int h   = pix >> 8;                 // block-uniform (256 = one row)

    __shared__ unsigned s_tact[2];            // 64-bit time-active batch mask
    __shared__ unsigned s_fbits[W_DIM];       // per-column freq channel-zero bits

    s_fbits[tid] = 0u;
    __syncthreads();                          // zero-init before atomics

    const int warp = tid >> 5;
    const int lane = tid & 31;

    // Time-active ballot (h uniform in block).
    if (warp < 2) {
        unsigned flag =
            ((unsigned)(h - __ldg(&time_starts[tid])) < (unsigned)MASK_LEN) ? 1u : 0u;
        unsigned bal = __ballot_sync(0xFFFFFFFFu, flag);
        if (lane == 0) s_tact[warp] = bal;
    }

    // Freq windows: 512 (b, lf) pairs distributed 2-per-thread (coalesced).
    #pragma unroll
    for (int rep = 0; rep < 2; ++rep) {
        const int p  = tid + rep * TPB;
        const int b  = p >> 3;
        const int lf = p & 7;
        const int fs = __ldg(&freq_starts[b]);
        float4 fr = __ldg(&freq_rand[((size_t)b * H_DIM + h) * MASK_LEN + lf]);
        unsigned bits = (fr.x < MASK_P ? 1u : 0u)
                      | (fr.y < MASK_P ? 2u : 0u)
                      | (fr.z < MASK_P ? 4u : 0u)
                      | (fr.w < MASK_P ? 8u : 0u);
        if (bits) atomicOr(&s_fbits[fs + lf], bits);
    }
    __syncthreads();                          // fbits + tact ready

    // Combine freq bits into the 4-channel multiplier for this column.
    const unsigned fb = s_fbits[w];
    float4 m;
    m.x = (fb & 1u) ? 0.f : 1.f;
    m.y = (fb & 2u) ? 0.f : 1.f;
    m.z = (fb & 4u) ? 0.f : 1.f;
    m.w = (fb & 8u) ? 0.f : 1.f;

    // Time contributions: iterate only active bits (expected ~1 of 64).
    #pragma unroll
    for (int half = 0; half < 2; ++half) {
        unsigned act = s_tact[half];
        while (act) {
            int b = half * 32 + (__ffs(act) - 1);
            act &= act - 1;
            int lt = h - __ldg(&time_starts[b]);     // in [0, 8)
            float4 tr = __ldg(&time_rand[(b * MASK_LEN + lt) * W_DIM + w]);
            if (tr.x < MASK_P) m.x = 0.f;
            if (tr.y < MASK_P) m.y = 0.f;
            if (tr.z < MASK_P) m.z = 0.f;
            if (tr.w < MASK_P) m.w = 0.f;
        }
    }

    // ---- stream this chunk's 16 batches (cs/cs, replicated config) ----
    const int b0 = blockIdx.y * B_PER_T;
    const float4* __restrict__ xp = x   + (size_t)b0 * HW + pix;
    float4*       __restrict__ op = out + (size_t)b0 * HW + pix;

    #pragma unroll
    for (int b = 0; b < B_PER_T; ++b) {
        float4 v = __ldcs(&xp[b * HW]);
        v.x *= m.x; v.y *= m.y; v.z *= m.z; v.w *= m.w;
        __stcs(&op[b * HW], v);
    }
}

extern "C" void kernel_launch(void* const* d_in, const int* in_sizes, int n_in,
                              void* d_out, int out_size)
{
    const float4* x    = (const float4*)d_in[0];
    const float4* tr   = (const float4*)d_in[1];
    const float4* fr   = (const float4*)d_in[2];
    const int*    ts   = (const int*)d_in[3];
    const int*    fs   = (const int*)d_in[4];
    float4*       out  = (float4*)d_out;

    dim3 grid(HW / TPB, BSPLIT);              // 512 x 4 = 2048 blocks
    fused_kernel<<<grid, TPB>>>(x, tr, fr, ts, fs, out);
}